// round 5
// baseline (speedup 1.0000x reference)
#include <cuda_runtime.h>
#include <cuda_bf16.h>

// Elementwise fused: out = (x + 2) + (x * 3) - (x - 1) * (x / 2)
//                       == fma(x, fma(-0.5, x, 4.5), 2)
// 8192 x 16384 fp32 = 134217728 elements = 33554432 float4s.
// Persistent single-wave kernel: 888 CTAs (148 SMs x 6 CTAs @ 40 regs),
// each looping with 8 front-batched LDG.128 (MLP=8), grid-stride layout,
// evict-first hints. No wave transitions.

__device__ __forceinline__ float fuse1(float v) {
    return fmaf(v, fmaf(-0.5f, v, 4.5f), 2.0f);
}

__device__ __forceinline__ float4 fuse4(float4 v) {
    float4 r;
    r.x = fuse1(v.x);
    r.y = fuse1(v.y);
    r.z = fuse1(v.z);
    r.w = fuse1(v.w);
    return r;
}

template <int UNROLL>
__global__ void fused_elemwise_persistent(const float4* __restrict__ x,
                                          float4* __restrict__ out,
                                          int n4) {
    const int stride = gridDim.x * blockDim.x;      // threads in grid
    const int big_stride = stride * UNROLL;
    int base = blockIdx.x * blockDim.x + threadIdx.x;

    // Full-tile iterations: all UNROLL lanes in range.
    while (base + (UNROLL - 1) * stride < n4) {
        float4 v[UNROLL];
#pragma unroll
        for (int k = 0; k < UNROLL; k++)
            v[k] = __ldcs(&x[base + k * stride]);   // front-batched, MLP=UNROLL
#pragma unroll
        for (int k = 0; k < UNROLL; k++)
            __stcs(&out[base + k * stride], fuse4(v[k]));
        base += big_stride;
    }
    // Remainder.
    for (int i = base; i < n4; i += stride)
        __stcs(&out[i], fuse4(__ldcs(&x[i])));
}

__global__ void fused_elemwise_tail(const float* __restrict__ x,
                                    float* __restrict__ out,
                                    int start, int n) {
    int i = start + blockIdx.x * blockDim.x + threadIdx.x;
    if (i < n) out[i] = fuse1(x[i]);
}

extern "C" void kernel_launch(void* const* d_in, const int* in_sizes, int n_in,
                              void* d_out, int out_size) {
    const float* x = (const float*)d_in[0];
    float* out = (float*)d_out;
    int n = in_sizes[0];

    int n4 = n / 4;
    if (n4 > 0) {
        constexpr int UNROLL = 8;
        const int threads = 256;
        // One resident wave: 148 SMs x 6 CTAs (40 regs/thread -> 6 CTAs/SM).
        int blocks = 148 * 6;
        // Never launch more threads than work items.
        int max_blocks = (n4 + threads - 1) / threads;
        if (blocks > max_blocks) blocks = max_blocks;
        fused_elemwise_persistent<UNROLL><<<blocks, threads>>>(
            (const float4*)x, (float4*)out, n4);
    }
    int rem = n - n4 * 4;
    if (rem > 0) {
        fused_elemwise_tail<<<1, 256>>>(x, out, n4 * 4, n);
    }
}

// round 6
// speedup vs baseline: 1.1299x; 1.1299x over previous
#include <cuda_runtime.h>
#include <cuda_bf16.h>

// Elementwise fused: out = (x + 2) + (x * 3) - (x - 1) * (x / 2)
//                       == fma(x, fma(-0.5, x, 4.5), 2)
// 8192 x 16384 fp32 = 134217728 elements = 33554432 float4s.
// Grid-stride (oversubscribed grid — beats persistent for streaming),
// 16 front-batched LDG.128 per thread (MLP=16), evict-first hints.

__device__ __forceinline__ float fuse1(float v) {
    return fmaf(v, fmaf(-0.5f, v, 4.5f), 2.0f);
}

__device__ __forceinline__ float4 fuse4(float4 v) {
    float4 r;
    r.x = fuse1(v.x);
    r.y = fuse1(v.y);
    r.z = fuse1(v.z);
    r.w = fuse1(v.w);
    return r;
}

template <int UNROLL>
__global__ void fused_elemwise_kernel(const float4* __restrict__ x,
                                      float4* __restrict__ out,
                                      int n4) {
    int stride = gridDim.x * blockDim.x;
    int base = blockIdx.x * blockDim.x + threadIdx.x;

    if (base + (UNROLL - 1) * stride < n4) {
        float4 v[UNROLL];
#pragma unroll
        for (int k = 0; k < UNROLL; k++)
            v[k] = __ldcs(&x[base + k * stride]);   // front-batched, MLP=UNROLL
#pragma unroll
        for (int k = 0; k < UNROLL; k++)
            __stcs(&out[base + k * stride], fuse4(v[k]));
    } else {
        for (int i = base; i < n4; i += stride)
            __stcs(&out[i], fuse4(__ldcs(&x[i])));
    }
}

__global__ void fused_elemwise_tail(const float* __restrict__ x,
                                    float* __restrict__ out,
                                    int start, int n) {
    int i = start + blockIdx.x * blockDim.x + threadIdx.x;
    if (i < n) out[i] = fuse1(x[i]);
}

extern "C" void kernel_launch(void* const* d_in, const int* in_sizes, int n_in,
                              void* d_out, int out_size) {
    const float* x = (const float*)d_in[0];
    float* out = (float*)d_out;
    int n = in_sizes[0];

    int n4 = n / 4;
    if (n4 > 0) {
        constexpr int UNROLL = 16;
        const int threads = 256;
        int total_threads = (n4 + UNROLL - 1) / UNROLL;
        int blocks = (total_threads + threads - 1) / threads;
        fused_elemwise_kernel<UNROLL><<<blocks, threads>>>(
            (const float4*)x, (float4*)out, n4);
    }
    int rem = n - n4 * 4;
    if (rem > 0) {
        fused_elemwise_tail<<<1, 256>>>(x, out, n4 * 4, n);
    }
}